// round 9
// baseline (speedup 1.0000x reference)
#include <cuda_runtime.h>
#include <math.h>
#include <stdint.h>

#define B_ 2
#define T_ 2048
#define C_ 1024
#define H_ 16
#define HS_ 64
#define NQKV 1152  // 1024 q + 64 k + 64 v

// Scratch (allocation-free rule: __device__ globals). All hold tf32-bit patterns.
__device__ float g_xt[B_ * T_ * C_];     // x, tf32 bits
__device__ float g_wqkvt[NQKV * C_];     // Wq‖Wk‖Wv, tf32 bits
__device__ float g_wpt[C_ * C_];         // Wp, tf32 bits
__device__ float g_qkv[B_ * T_ * NQKV];  // qkv output: q pre-scaled tf32 bits, k/v tf32 bits
__device__ float g_y[B_ * T_ * C_];      // attn output, tf32 bits

__device__ __forceinline__ uint32_t f2tf(float f) {
    uint32_t u;
    asm("cvt.rna.tf32.f32 %0, %1;" : "=r"(u) : "f"(f));
    return u;
}

__device__ __forceinline__ uint32_t smaddr(const void* p) {
    return (uint32_t)__cvta_generic_to_shared(p);
}

__device__ __forceinline__ void cp16(uint32_t s, const void* g) {
    asm volatile("cp.async.cg.shared.global [%0], [%1], 16;" :: "r"(s), "l"(g));
}

__device__ __forceinline__ void mma_tf32(float c[4], const uint32_t* a, const uint32_t* b) {
    asm volatile(
        "mma.sync.aligned.m16n8k8.row.col.f32.tf32.tf32.f32 "
        "{%0,%1,%2,%3}, {%4,%5,%6,%7}, {%8,%9}, {%0,%1,%2,%3};"
        : "+f"(c[0]), "+f"(c[1]), "+f"(c[2]), "+f"(c[3])
        : "r"(a[0]), "r"(a[1]), "r"(a[2]), "r"(a[3]), "r"(b[0]), "r"(b[1]));
}

// One-shot rna tf32 conversion of x, concat(Wq,Wk,Wv), Wp. 1,605,632 float4s.
__global__ __launch_bounds__(256) void conv_tf(const float* __restrict__ x,
                                               const float* __restrict__ Wk,
                                               const float* __restrict__ Wv,
                                               const float* __restrict__ Wq,
                                               const float* __restrict__ Wp,
                                               float* __restrict__ xt,
                                               float* __restrict__ wqkvt,
                                               float* __restrict__ wpt) {
    int idx = blockIdx.x * 256 + threadIdx.x;
    const int X4 = B_ * T_ * C_ / 4;      // 1048576
    const int WQKV4 = NQKV * C_ / 4;      // 294912
    float4 f;
    float4* dst;
    if (idx < X4) {
        f = ((const float4*)x)[idx];
        dst = (float4*)xt + idx;
    } else if (idx < X4 + WQKV4) {
        int w4 = idx - X4;
        int row = w4 >> 8, c4 = w4 & 255;
        const float4* src = row < 1024 ? (const float4*)Wq + row * 256 + c4
                          : row < 1088 ? (const float4*)Wk + (row - 1024) * 256 + c4
                                       : (const float4*)Wv + (row - 1088) * 256 + c4;
        f = *src;
        dst = (float4*)wqkvt + w4;
    } else {
        int w4 = idx - X4 - WQKV4;
        f = ((const float4*)Wp)[w4];
        dst = (float4*)wpt + w4;
    }
    uint4 u = make_uint4(f2tf(f.x), f2tf(f.y), f2tf(f.z), f2tf(f.w));
    *(uint4*)dst = u;
}

// C[m,n] = sum_k A[m,k]*W[n,k] (+bias). A/W already tf32 bits -> raw copies, no cvt.
// BM=128, BK=32, BN=128; 256 thr = 8 warps (4m x 2n). Double-buffered smem,
// register prefetch, ONE barrier per K-iter.
// QKVEPI: cols<1024 (q) stored as f2tf(0.125*acc); cols>=1024 (k/v) as f2tf(acc).
template <bool BIAS, bool QKVEPI>
__global__ __launch_bounds__(256) void gemm_tc(const float* __restrict__ A,
                                               const float* __restrict__ W,
                                               const float* __restrict__ bias,
                                               float* __restrict__ C,
                                               int N, int K) {
    extern __shared__ __align__(16) uint32_t smp[];
    const int ASZ = 128 * 36;  // As0 | As1 | Bs0 | Bs1
    int tid = threadIdx.x, lane = tid & 31, warp = tid >> 5;
    int g = lane >> 2, q4 = lane & 3;
    int wm = warp & 3, wn = warp >> 2;
    int bm = blockIdx.y * 128, bn = blockIdx.x * 128;
    int lr = tid >> 3, lc4 = (tid & 7) * 4;

    float acc[2][8][4];
#pragma unroll
    for (int mt = 0; mt < 2; mt++)
#pragma unroll
        for (int j = 0; j < 8; j++)
#pragma unroll
            for (int e = 0; e < 4; e++) acc[mt][j][e] = 0.f;

    const float* arow[4];
    const float* wrow[4];
#pragma unroll
    for (int t = 0; t < 4; t++) {
        arow[t] = A + (size_t)(bm + lr + 32 * t) * K + lc4;
        wrow[t] = W + (size_t)(bn + lr + 32 * t) * K + lc4;
    }

    uint4 pa[4], pb[4];
#pragma unroll
    for (int t = 0; t < 4; t++) {
        pa[t] = *(const uint4*)(arow[t]);
        pb[t] = *(const uint4*)(wrow[t]);
    }
#pragma unroll
    for (int t = 0; t < 4; t++) {
        *(uint4*)&smp[(lr + t * 32) * 36 + lc4] = pa[t];
        *(uint4*)&smp[2 * ASZ + (lr + t * 32) * 36 + lc4] = pb[t];
    }
    __syncthreads();

    for (int k0 = 0; k0 < K; k0 += 32) {
        int cur = (k0 >> 5) & 1;
        bool more = (k0 + 32) < K;
        if (more) {
#pragma unroll
            for (int t = 0; t < 4; t++) {
                pa[t] = *(const uint4*)(arow[t] + k0 + 32);
                pb[t] = *(const uint4*)(wrow[t] + k0 + 32);
            }
        }
        const uint32_t* Asb = smp + cur * ASZ;
        const uint32_t* Bsb = smp + 2 * ASZ + cur * ASZ;
#pragma unroll
        for (int kk = 0; kk < 4; kk++) {
            uint32_t af[2][4], bf[8][2];
#pragma unroll
            for (int mt = 0; mt < 2; mt++) {
                int rb = wm * 32 + mt * 16;
                af[mt][0] = Asb[(rb + g) * 36 + kk * 8 + q4];
                af[mt][1] = Asb[(rb + g + 8) * 36 + kk * 8 + q4];
                af[mt][2] = Asb[(rb + g) * 36 + kk * 8 + q4 + 4];
                af[mt][3] = Asb[(rb + g + 8) * 36 + kk * 8 + q4 + 4];
            }
#pragma unroll
            for (int j = 0; j < 8; j++) {
                int nb = wn * 64 + j * 8 + g;
                bf[j][0] = Bsb[nb * 36 + kk * 8 + q4];
                bf[j][1] = Bsb[nb * 36 + kk * 8 + q4 + 4];
            }
#pragma unroll
            for (int mt = 0; mt < 2; mt++)
#pragma unroll
                for (int j = 0; j < 8; j++) mma_tf32(acc[mt][j], af[mt], bf[j]);
        }
        if (more) {
            uint32_t* Asn = smp + (1 - cur) * ASZ;
            uint32_t* Bsn = smp + 2 * ASZ + (1 - cur) * ASZ;
#pragma unroll
            for (int t = 0; t < 4; t++) {
                *(uint4*)&Asn[(lr + t * 32) * 36 + lc4] = pa[t];
                *(uint4*)&Bsn[(lr + t * 32) * 36 + lc4] = pb[t];
            }
            __syncthreads();
        }
    }

#pragma unroll
    for (int mt = 0; mt < 2; mt++)
#pragma unroll
        for (int j = 0; j < 8; j++) {
            int row = bm + wm * 32 + mt * 16 + g;
            int col = bn + wn * 64 + j * 8 + 2 * q4;
            float2 v0 = make_float2(acc[mt][j][0], acc[mt][j][1]);
            float2 v1 = make_float2(acc[mt][j][2], acc[mt][j][3]);
            if (BIAS) {
                float b0 = bias[col], b1 = bias[col + 1];
                v0.x += b0; v0.y += b1; v1.x += b0; v1.y += b1;
            }
            if (QKVEPI) {
                float sc = (col < 1024) ? 0.125f : 1.0f;
                v0.x = __uint_as_float(f2tf(sc * v0.x));
                v0.y = __uint_as_float(f2tf(sc * v0.y));
                v1.x = __uint_as_float(f2tf(sc * v1.x));
                v1.y = __uint_as_float(f2tf(sc * v1.y));
            }
            *(float2*)&C[(size_t)row * N + col] = v0;
            *(float2*)&C[(size_t)(row + 8) * N + col] = v1;
        }
}

// Flash-style causal MQA attention, tf32 tensor cores.
// 128 thr = 4 warps; each warp owns 32 query rows (2 m16 tiles) -> K/V frags shared
// across both tiles (halved LDS bytes per row). 64-key cp.async double-buffered tiles;
// softmax in 32-key chunks to cap live registers.
// q remap quirk: q[b,h,t,:] = qkv[b, h*128 + t/16, (t%16)*64 .. +64).
__global__ __launch_bounds__(128) void attn_tc(const uint32_t* __restrict__ qkv,
                                               uint32_t* __restrict__ y) {
    extern __shared__ __align__(16) uint32_t smp[];
    const int KSZ = 64 * 68, VSZ = 64 * 72;  // Ks0|Ks1|Vs0|Vs1
    int bid = blockIdx.x;
    int qt = 15 - (bid >> 5);  // LPT: longest first
    int bh = bid & 31;
    int b = bh >> 4, h = bh & 15;
    int tid = threadIdx.x, lane = tid & 31, warp = tid >> 5;
    int g = lane >> 2, q4 = lane & 3;
    const uint32_t* base = qkv + (size_t)b * T_ * NQKV;
    int wrmin = qt * 128 + warp * 32, wrmax = wrmin + 31;

    // Q fragments for both m-tiles (already 0.125-scaled tf32 bits)
    uint32_t qa[2][8][4];
#pragma unroll
    for (int mt = 0; mt < 2; mt++) {
        int r0 = wrmin + mt * 16 + g, r1 = r0 + 8;
        size_t a0 = (size_t)(h * 128 + (r0 >> 4)) * NQKV + (r0 & 15) * 64;
        size_t a1 = (size_t)(h * 128 + (r1 >> 4)) * NQKV + (r1 & 15) * 64;
#pragma unroll
        for (int kk = 0; kk < 8; kk++) {
            qa[mt][kk][0] = base[a0 + kk * 8 + q4];
            qa[mt][kk][1] = base[a1 + kk * 8 + q4];
            qa[mt][kk][2] = base[a0 + kk * 8 + q4 + 4];
            qa[mt][kk][3] = base[a1 + kk * 8 + q4 + 4];
        }
    }

    float o[2][8][4];
#pragma unroll
    for (int mt = 0; mt < 2; mt++)
#pragma unroll
        for (int j = 0; j < 8; j++)
#pragma unroll
            for (int e = 0; e < 4; e++) o[mt][j][e] = 0.f;
    float m_[2][2] = {{-INFINITY, -INFINITY}, {-INFINITY, -INFINITY}};
    float l_[2][2] = {{0.f, 0.f}, {0.f, 0.f}};

    int nkt = qt * 2 + 2;
    int srcA = (lane & ~3) | (q4 >> 1);
    int srcB = srcA + 2;
    bool sel = (q4 & 1) != 0;

    // Stage full 64x64 K and V tiles: 1024 16B-chunks each, 128 threads x 8 iters.
    auto stage = [&](int kt, int bi) {
#pragma unroll
        for (int t = 0; t < 8; t++) {
            int ck = tid + t * 128;        // 0..1023
            int r = ck >> 4, c = (ck & 15) * 4;
            size_t row = (size_t)(kt * 64 + r) * NQKV;
            cp16(smaddr(&smp[bi * KSZ + r * 68 + c]), base + row + 1024 + c);
            cp16(smaddr(&smp[2 * KSZ + bi * VSZ + r * 72 + c]), base + row + 1088 + c);
        }
        asm volatile("cp.async.commit_group;");
    };

    stage(0, 0);

    for (int kt = 0; kt < nkt; kt++) {
        if (kt + 1 < nkt) {
            stage(kt + 1, (kt + 1) & 1);
            asm volatile("cp.async.wait_group 1;");
        } else {
            asm volatile("cp.async.wait_group 0;");
        }
        __syncthreads();

        int ktb = kt * 64;
        if (ktb <= wrmax) {
            const uint32_t* Kc = smp + (kt & 1) * KSZ;
            const uint32_t* Vc = smp + 2 * KSZ + (kt & 1) * VSZ;
#pragma unroll
            for (int c = 0; c < 2; c++) {  // 32-key chunks
                int ckb = ktb + c * 32;
                if (ckb > wrmax) break;

                // S = Q K^T for both m-tiles, sharing K b-frags
                float s[2][4][4];
#pragma unroll
                for (int mt = 0; mt < 2; mt++)
#pragma unroll
                    for (int jj = 0; jj < 4; jj++)
#pragma unroll
                        for (int e = 0; e < 4; e++) s[mt][jj][e] = 0.f;
#pragma unroll
                for (int kk = 0; kk < 8; kk++) {
                    uint32_t bf[4][2];
#pragma unroll
                    for (int jj = 0; jj < 4; jj++) {
                        int kr = c * 32 + jj * 8 + g;
                        bf[jj][0] = Kc[kr * 68 + kk * 8 + q4];
                        bf[jj][1] = Kc[kr * 68 + kk * 8 + q4 + 4];
                    }
#pragma unroll
                    for (int mt = 0; mt < 2; mt++)
#pragma unroll
                        for (int jj = 0; jj < 4; jj++)
                            mma_tf32(s[mt][jj], qa[mt][kk], bf[jj]);
                }

                // mask + online softmax per m-tile
                bool needmask = (ckb + 31) > wrmin;
#pragma unroll
                for (int mt = 0; mt < 2; mt++) {
                    int rm0 = wrmin + mt * 16 + g, rm1 = rm0 + 8;
                    float t0 = -INFINITY, t1 = -INFINITY;
#pragma unroll
                    for (int jj = 0; jj < 4; jj++) {
                        if (needmask) {
                            int tk = ckb + jj * 8 + 2 * q4;
                            if (tk > rm0) s[mt][jj][0] = -INFINITY;
                            if (tk + 1 > rm0) s[mt][jj][1] = -INFINITY;
                            if (tk > rm1) s[mt][jj][2] = -INFINITY;
                            if (tk + 1 > rm1) s[mt][jj][3] = -INFINITY;
                        }
                        t0 = fmaxf(t0, fmaxf(s[mt][jj][0], s[mt][jj][1]));
                        t1 = fmaxf(t1, fmaxf(s[mt][jj][2], s[mt][jj][3]));
                    }
                    t0 = fmaxf(t0, __shfl_xor_sync(0xffffffffu, t0, 1));
                    t0 = fmaxf(t0, __shfl_xor_sync(0xffffffffu, t0, 2));
                    t1 = fmaxf(t1, __shfl_xor_sync(0xffffffffu, t1, 1));
                    t1 = fmaxf(t1, __shfl_xor_sync(0xffffffffu, t1, 2));
                    float mn0 = fmaxf(m_[mt][0], t0), mn1 = fmaxf(m_[mt][1], t1);
                    float cr0 = __expf(m_[mt][0] - mn0), cr1 = __expf(m_[mt][1] - mn1);
                    m_[mt][0] = mn0; m_[mt][1] = mn1;
                    l_[mt][0] *= cr0; l_[mt][1] *= cr1;
#pragma unroll
                    for (int j = 0; j < 8; j++) {
                        o[mt][j][0] *= cr0; o[mt][j][1] *= cr0;
                        o[mt][j][2] *= cr1; o[mt][j][3] *= cr1;
                    }
#pragma unroll
                    for (int jj = 0; jj < 4; jj++) {
                        s[mt][jj][0] = __expf(s[mt][jj][0] - mn0);
                        s[mt][jj][1] = __expf(s[mt][jj][1] - mn0);
                        s[mt][jj][2] = __expf(s[mt][jj][2] - mn1);
                        s[mt][jj][3] = __expf(s[mt][jj][3] - mn1);
                        l_[mt][0] += s[mt][jj][0] + s[mt][jj][1];
                        l_[mt][1] += s[mt][jj][2] + s[mt][jj][3];
                    }
                }

                // O += P V: shuffle C-frags to A-frags; V b-frags shared across m-tiles
#pragma unroll
                for (int kk2 = 0; kk2 < 4; kk2++) {
                    uint32_t pa2[2][4];
#pragma unroll
                    for (int mt = 0; mt < 2; mt++) {
                        float x0 = __shfl_sync(0xffffffffu, s[mt][kk2][0], srcA);
                        float x1 = __shfl_sync(0xffffffffu, s[mt][kk2][1], srcA);
                        float x2 = __shfl_sync(0xffffffffu, s[mt][kk2][2], srcA);
                        float x3 = __shfl_sync(0xffffffffu, s[mt][kk2][3], srcA);
                        float y0 = __shfl_sync(0xffffffffu, s[mt][kk2][0], srcB);
                        float y1 = __shfl_sync(0xffffffffu, s[mt][kk2][1], srcB);
                        float y2 = __shfl_sync(0xffffffffu, s[mt][kk2][2], srcB);
                        float y3 = __shfl_sync(0xffffffffu, s[mt][kk2][3], srcB);
                        pa2[mt][0] = f2tf(sel ? x1 : x0);
                        pa2[mt][1] = f2tf(sel ? x3 : x2);
                        pa2[mt][2] = f2tf(sel ? y1 : y0);
                        pa2[mt][3] = f2tf(sel ? y3 : y2);
                    }
                    int kr0 = c * 32 + kk2 * 8 + q4;
                    uint32_t bfv[8][2];
#pragma unroll
                    for (int j = 0; j < 8; j++) {
                        bfv[j][0] = Vc[kr0 * 72 + j * 8 + g];
                        bfv[j][1] = Vc[(kr0 + 4) * 72 + j * 8 + g];
                    }
#pragma unroll
                    for (int mt = 0; mt < 2; mt++)
#pragma unroll
                        for (int j = 0; j < 8; j++)
                            mma_tf32(o[mt][j], pa2[mt], bfv[j]);
                }
            }
        }
        __syncthreads();
    }

#pragma unroll
    for (int mt = 0; mt < 2; mt++) {
        float la = l_[mt][0], lb = l_[mt][1];
        la += __shfl_xor_sync(0xffffffffu, la, 1);
        la += __shfl_xor_sync(0xffffffffu, la, 2);
        lb += __shfl_xor_sync(0xffffffffu, lb, 1);
        lb += __shfl_xor_sync(0xffffffffu, lb, 2);
        float i0 = 1.f / la, i1 = 1.f / lb;
        int r0 = wrmin + mt * 16 + g, r1 = r0 + 8;
        uint32_t* yb = y + (size_t)b * T_ * C_;
#pragma unroll
        for (int j = 0; j < 8; j++) {
            int col = h * 64 + j * 8 + 2 * q4;
            *(uint2*)&yb[(size_t)r0 * C_ + col] =
                make_uint2(f2tf(o[mt][j][0] * i0), f2tf(o[mt][j][1] * i0));
            *(uint2*)&yb[(size_t)r1 * C_ + col] =
                make_uint2(f2tf(o[mt][j][2] * i1), f2tf(o[mt][j][3] * i1));
        }
    }
}

extern "C" void kernel_launch(void* const* d_in, const int* in_sizes, int n_in,
                              void* d_out, int out_size) {
    (void)in_sizes; (void)n_in; (void)out_size;
    const float* x  = (const float*)d_in[0];
    const float* Wk = (const float*)d_in[1];
    const float* Wv = (const float*)d_in[2];
    const float* Wq = (const float*)d_in[3];
    const float* Wp = (const float*)d_in[4];
    const float* bp = (const float*)d_in[5];
    float* out = (float*)d_out;

    float *xt, *wqkvt, *wpt, *qkvb, *yb;
    cudaGetSymbolAddress((void**)&xt, g_xt);
    cudaGetSymbolAddress((void**)&wqkvt, g_wqkvt);
    cudaGetSymbolAddress((void**)&wpt, g_wpt);
    cudaGetSymbolAddress((void**)&qkvb, g_qkv);
    cudaGetSymbolAddress((void**)&yb, g_y);

    const int GEMM_SMEM = 4 * 128 * 36 * 4;                 // 73728 B
    const int ATTN_SMEM = (2 * 64 * 68 + 2 * 64 * 72) * 4;  // 71680 B
    cudaFuncSetAttribute(gemm_tc<false, true>,
                         cudaFuncAttributeMaxDynamicSharedMemorySize, GEMM_SMEM);
    cudaFuncSetAttribute(gemm_tc<true, false>,
                         cudaFuncAttributeMaxDynamicSharedMemorySize, GEMM_SMEM);
    cudaFuncSetAttribute(attn_tc,
                         cudaFuncAttributeMaxDynamicSharedMemorySize, ATTN_SMEM);

    // One-shot tf32 conversion of all GEMM inputs
    conv_tf<<<6272, 256>>>(x, Wk, Wv, Wq, Wp, xt, wqkvt, wpt);
    // Fused qkv projection: [4096,1152]; epilogue emits tf32 bits (q pre-scaled)
    gemm_tc<false, true><<<dim3(9, 32), 256, GEMM_SMEM>>>(xt, wqkvt, nullptr, qkvb,
                                                          NQKV, 1024);
    // attention -> y (tf32 bits, head-transposed layout baked in)
    attn_tc<<<512, 128, ATTN_SMEM>>>((const uint32_t*)qkvb, (uint32_t*)yb);
    // out = y @ Wp.T + bp (fp32 output)
    gemm_tc<true, false><<<dim3(8, 32), 256, GEMM_SMEM>>>(yb, wpt, bp, out, 1024, 1024);
}